// round 2
// baseline (speedup 1.0000x reference)
#include <cuda_runtime.h>
#include <math.h>

#define B_   16
#define L_   1024
#define H_   8
#define E_   64
#define D_   512
#define LF   513
#define NROW 8192            // B_*D_
#define AP   65

// ---------------- device scratch (no cudaMalloc allowed) -------------------
__device__ float  g_q2t[B_ * D_ * L_];
__device__ float  g_qf_re[NROW * LF];
__device__ float  g_qf_im[NROW * LF];
__device__ float  g_kf_re[NROW * LF];
__device__ float  g_kf_im[NROW * LF];
__device__ float  g_vf_re[NROW * LF];
__device__ float  g_vf_im[NROW * LF];
__device__ float  g_of_re[NROW * LF];
__device__ float  g_of_im[NROW * LF];
__device__ float2 g_tw[512];

// ---------------- packed f32x2 helpers ------------------------------------
__device__ __forceinline__ unsigned long long pk2(float lo, float hi) {
    unsigned long long r;
    asm("mov.b64 %0, {%1, %2};" : "=l"(r) : "f"(lo), "f"(hi));
    return r;
}
__device__ __forceinline__ void upk2(unsigned long long v, float& lo, float& hi) {
    asm("mov.b64 {%0, %1}, %2;" : "=f"(lo), "=f"(hi) : "l"(v));
}
__device__ __forceinline__ unsigned long long ffma2(unsigned long long a,
                                                    unsigned long long b,
                                                    unsigned long long c) {
    unsigned long long d;
    asm("fma.rn.f32x2 %0, %1, %2, %3;" : "=l"(d) : "l"(a), "l"(b), "l"(c));
    return d;
}
__device__ __forceinline__ float sigmoidf_(float x) {
    return 1.0f / (1.0f + expf(-x));
}

// ---------------- twiddle table: exp(+2*pi*i*j/1024) -----------------------
__global__ void twiddle_kernel() {
    int j = threadIdx.x;
    if (j < 512) {
        float s, c;
        sincosf(6.283185307179586f * (float)j * (1.0f / 1024.0f), &s, &c);
        g_tw[j] = make_float2(c, s);
    }
}

// ---------------- Conv1d(512->1024,k=3,p=1) + GLU -> g_q2t[b,c,l] ----------
__global__ __launch_bounds__(256) void conv_glu_kernel(
        const float* __restrict__ q, const float* __restrict__ W,
        const float* __restrict__ bias) {
    __shared__ __align__(16) float pool[7200];
    float* sx  = pool;               // [16 ic][66 l]
    float* swa = pool + 1056;        // [48 r][64 oc]  r = ic*3+kw
    float* swg = pool + 1056 + 3072;

    int b   = blockIdx.x >> 4;
    int l0  = (blockIdx.x & 15) << 6;
    int oc0 = blockIdx.y << 6;
    int tid = threadIdx.x;
    int tx  = tid & 15, ty = tid >> 4;

    unsigned long long pa[4][2], pg[4][2];
#pragma unroll
    for (int i = 0; i < 4; i++) {
        pa[i][0] = pa[i][1] = 0ull;
        pg[i][0] = pg[i][1] = 0ull;
    }

    for (int ic0 = 0; ic0 < 512; ic0 += 16) {
        __syncthreads();
#pragma unroll
        for (int t = 0; t < 5; t++) {
            int idx = tid + (t << 8);
            if (idx < 1056) {
                int li = idx >> 4, kk = idx & 15;
                int l = l0 - 1 + li;
                float v = 0.0f;
                if ((unsigned)l < 1024u)
                    v = q[((size_t)b * 1024 + l) * 512 + ic0 + kk];
                sx[kk * 66 + li] = v;
            }
        }
#pragma unroll
        for (int t = 0; t < 12; t++) {
            int idx = tid + (t << 8);
            int oc = idx / 48, r = idx % 48;
            swa[r * 64 + oc] = W[(size_t)(oc0 + oc) * 1536 + ic0 * 3 + r];
        }
#pragma unroll
        for (int t = 0; t < 12; t++) {
            int idx = tid + (t << 8);
            int oc = idx / 48, r = idx % 48;
            swg[r * 64 + oc] = W[(size_t)(512 + oc0 + oc) * 1536 + ic0 * 3 + r];
        }
        __syncthreads();

#pragma unroll
        for (int kk = 0; kk < 16; kk++) {
            unsigned long long xm[4], x0[4], xp[4];
#pragma unroll
            for (int yl = 0; yl < 4; yl++) {
                int li = (ty << 2) + yl;
                float a  = sx[kk * 66 + li];
                float b2 = sx[kk * 66 + li + 1];
                float c2 = sx[kk * 66 + li + 2];
                xm[yl] = pk2(a, a); x0[yl] = pk2(b2, b2); xp[yl] = pk2(c2, c2);
            }
#pragma unroll
            for (int xl2 = 0; xl2 < 2; xl2++) {
                int oc = (tx << 2) + (xl2 << 1);
                unsigned long long wa0 = *(const unsigned long long*)(swa + (kk * 3 + 0) * 64 + oc);
                unsigned long long wa1 = *(const unsigned long long*)(swa + (kk * 3 + 1) * 64 + oc);
                unsigned long long wa2 = *(const unsigned long long*)(swa + (kk * 3 + 2) * 64 + oc);
                unsigned long long wg0 = *(const unsigned long long*)(swg + (kk * 3 + 0) * 64 + oc);
                unsigned long long wg1 = *(const unsigned long long*)(swg + (kk * 3 + 1) * 64 + oc);
                unsigned long long wg2 = *(const unsigned long long*)(swg + (kk * 3 + 2) * 64 + oc);
#pragma unroll
                for (int yl = 0; yl < 4; yl++) {
                    pa[yl][xl2] = ffma2(xm[yl], wa0, pa[yl][xl2]);
                    pa[yl][xl2] = ffma2(x0[yl], wa1, pa[yl][xl2]);
                    pa[yl][xl2] = ffma2(xp[yl], wa2, pa[yl][xl2]);
                    pg[yl][xl2] = ffma2(xm[yl], wg0, pg[yl][xl2]);
                    pg[yl][xl2] = ffma2(x0[yl], wg1, pg[yl][xl2]);
                    pg[yl][xl2] = ffma2(xp[yl], wg2, pg[yl][xl2]);
                }
            }
        }
    }

    __syncthreads();
    float* st = pool;                // [64 oc][65 l]
#pragma unroll
    for (int yl = 0; yl < 4; yl++) {
#pragma unroll
        for (int xl2 = 0; xl2 < 2; xl2++) {
            float a0, a1, g0, g1;
            upk2(pa[yl][xl2], a0, a1);
            upk2(pg[yl][xl2], g0, g1);
            int oc = (tx << 2) + (xl2 << 1);
            a0 += bias[oc0 + oc];       a1 += bias[oc0 + oc + 1];
            g0 += bias[512 + oc0 + oc]; g1 += bias[512 + oc0 + oc + 1];
            int li = (ty << 2) + yl;
            st[oc * 65 + li]       = a0 * sigmoidf_(g0);
            st[(oc + 1) * 65 + li] = a1 * sigmoidf_(g1);
        }
    }
    __syncthreads();
#pragma unroll
    for (int t = 0; t < 16; t++) {
        int idx = tid + (t << 8);
        int c = idx >> 6, li = idx & 63;
        g_q2t[((size_t)b * 512 + oc0 + c) * 1024 + l0 + li] = st[c * 65 + li];
    }
}

// ---------------- 1024-pt radix-2 Stockham (DIF, natural order) ------------
__device__ __forceinline__ void fft1024_shared(float2* bufA, float2* bufB,
                                               float sgn, int tid) {
    float2* src = bufA;
    float2* dst = bufB;
    int m = 1;
#pragma unroll
    for (int stage = 0; stage < 10; stage++) {
#pragma unroll
        for (int u = 0; u < 2; u++) {
            int idx = tid + (u << 8);
            float2 c0 = src[idx];
            float2 c1 = src[idx + 512];
            int k = idx & (m - 1);
            int o = idx + (idx - k);
            float2 w = g_tw[idx - k];
            float wy = w.y * sgn;
            float trx = c0.x - c1.x, trY = c0.y - c1.y;
            dst[o]     = make_float2(c0.x + c1.x, c0.y + c1.y);
            dst[o + m] = make_float2(w.x * trx - wy * trY, w.x * trY + wy * trx);
        }
        __syncthreads();
        float2* t = src; src = dst; dst = t;
        m <<= 1;
    }
    // after 10 swaps result is in bufA
}

// which: 0 = q (g_q2t contiguous), 1 = k, 2 = v ([B,S,H,E] strided)
__global__ __launch_bounds__(256) void rfft_kernel(const float* __restrict__ in,
                                                   int which) {
    __shared__ float2 bufA[1024];
    __shared__ float2 bufB[1024];
    int row = blockIdx.x, tid = threadIdx.x;
    if (which == 0) {
        const float* p = g_q2t + (size_t)row * 1024;
        for (int i = tid; i < 1024; i += 256) bufA[i] = make_float2(p[i], 0.0f);
    } else {
        const float* p = in + (size_t)(row >> 9) * 524288 + (row & 511);
        for (int i = tid; i < 1024; i += 256)
            bufA[i] = make_float2(p[(size_t)i * 512], 0.0f);
    }
    __syncthreads();
    fft1024_shared(bufA, bufB, -1.0f, tid);
    float* ore = (which == 0) ? g_qf_re : (which == 1) ? g_kf_re : g_vf_re;
    float* oim = (which == 0) ? g_qf_im : (which == 1) ? g_kf_im : g_vf_im;
    for (int i = tid; i < 513; i += 256) {
        float2 vv = bufA[i];
        ore[(size_t)row * 513 + i] = vv.x * 0.03125f;
        oim[(size_t)row * 513 + i] = vv.y * 0.03125f;
    }
}

// ---------------- fused frequency attention (flash-style) ------------------
__global__ __launch_bounds__(256) void attn_kernel() {
    extern __shared__ float sm[];
    float* Qre = sm;
    float* Qim = Qre + 64 * AP;
    float* Ure = Qim + 64 * AP;
    float* Uim = Ure + 64 * AP;
    float* Tre = Uim + 64 * AP;
    float* Tim = Tre + 64 * AP;

    int bh  = blockIdx.y;
    int x0  = blockIdx.x << 6;
    int tid = threadIdx.x;
    int tx  = tid & 15, ty = tid >> 4;
    size_t base = (size_t)bh * 64 * 513;

#pragma unroll
    for (int t = 0; t < 16; t++) {
        int idx = tid + (t << 8);
        int e = idx >> 6, xi = idx & 63;
        int x = x0 + xi;
        float vr = 0.0f, vi = 0.0f;
        if (x < 513) {
            vr = g_qf_re[base + (size_t)e * 513 + x];
            vi = g_qf_im[base + (size_t)e * 513 + x];
        }
        Qre[e * AP + xi] = vr;
        Qim[e * AP + xi] = vi;
    }

    float ofre[4][4] = {}, ofim[4][4] = {};
    float Dacc[4] = {};

    for (int yt = 0; yt < 9; yt++) {
        int y0 = yt << 6;
        __syncthreads();
#pragma unroll
        for (int t = 0; t < 16; t++) {
            int idx = tid + (t << 8);
            int e = idx >> 6, yi = idx & 63;
            int y = y0 + yi;
            float vr = 0.0f, vi = 0.0f;
            if (y < 513) {
                vr = g_kf_re[base + (size_t)e * 513 + y];
                vi = g_kf_im[base + (size_t)e * 513 + y];
            }
            Ure[e * AP + yi] = vr;
            Uim[e * AP + yi] = vi;
        }
        __syncthreads();

        float sre[4][4] = {}, sim[4][4] = {};
#pragma unroll 8
        for (int e = 0; e < 64; e++) {
            float qr[4], qi[4], kr[4], ki[4];
#pragma unroll
            for (int i = 0; i < 4; i++) {
                qr[i] = Qre[e * AP + (ty << 2) + i];
                qi[i] = Qim[e * AP + (ty << 2) + i];
            }
#pragma unroll
            for (int j = 0; j < 4; j++) {
                kr[j] = Ure[e * AP + (tx << 2) + j];
                ki[j] = Uim[e * AP + (tx << 2) + j];
            }
#pragma unroll
            for (int i = 0; i < 4; i++)
#pragma unroll
                for (int j = 0; j < 4; j++) {
                    sre[i][j] += qr[i] * kr[j] + qi[i] * ki[j];
                    sim[i][j] += qi[i] * kr[j] - qr[i] * ki[j];
                }
        }
        __syncthreads();

#pragma unroll
        for (int i = 0; i < 4; i++)
#pragma unroll
            for (int j = 0; j < 4; j++) {
                float sr = sre[i][j] * 0.125f;
                float si = sim[i][j] * 0.125f;
                float mg = sqrtf(sr * sr + si * si);
                float w  = 1.0f + sigmoidf_(mg);
                Dacc[i] += mg * w;
                Tre[((ty << 2) + i) * AP + (tx << 2) + j] = sr * w;
                Tim[((ty << 2) + i) * AP + (tx << 2) + j] = si * w;
            }
#pragma unroll
        for (int t = 0; t < 16; t++) {
            int idx = tid + (t << 8);
            int e = idx >> 6, yi = idx & 63;
            int y = y0 + yi;
            float vr = 0.0f, vi = 0.0f;
            if (y < 513) {
                vr = g_vf_re[base + (size_t)e * 513 + y];
                vi = g_vf_im[base + (size_t)e * 513 + y];
            }
            Ure[e * AP + yi] = vr;
            Uim[e * AP + yi] = vi;
        }
        __syncthreads();

#pragma unroll 8
        for (int y = 0; y < 64; y++) {
            float tr[4], ti[4], vr[4], vi[4];
#pragma unroll
            for (int i = 0; i < 4; i++) {
                tr[i] = Tre[((ty << 2) + i) * AP + y];
                ti[i] = Tim[((ty << 2) + i) * AP + y];
            }
#pragma unroll
            for (int j = 0; j < 4; j++) {
                vr[j] = Ure[((tx << 2) + j) * AP + y];
                vi[j] = Uim[((tx << 2) + j) * AP + y];
            }
#pragma unroll
            for (int i = 0; i < 4; i++)
#pragma unroll
                for (int j = 0; j < 4; j++) {
                    ofre[i][j] += tr[i] * vr[j] - ti[i] * vi[j];
                    ofim[i][j] += tr[i] * vi[j] + ti[i] * vr[j];
                }
        }
    }

#pragma unroll
    for (int i = 0; i < 4; i++) {
        float dsum = Dacc[i];
        dsum += __shfl_xor_sync(0xffffffffu, dsum, 1);
        dsum += __shfl_xor_sync(0xffffffffu, dsum, 2);
        dsum += __shfl_xor_sync(0xffffffffu, dsum, 4);
        dsum += __shfl_xor_sync(0xffffffffu, dsum, 8);
        Dacc[i] = 1.0f / fmaxf(dsum, 1e-12f);
    }
#pragma unroll
    for (int i = 0; i < 4; i++) {
        int x = x0 + (ty << 2) + i;
        if (x < 513) {
#pragma unroll
            for (int j = 0; j < 4; j++) {
                int e = (tx << 2) + j;
                g_of_re[base + (size_t)e * 513 + x] = ofre[i][j] * Dacc[i];
                g_of_im[base + (size_t)e * 513 + x] = ofim[i][j] * Dacc[i];
            }
        }
    }
}

// ---------------- irfft (ortho) + scatter to out[b,l,h,e] ------------------
__global__ __launch_bounds__(256) void irfft_kernel(float* __restrict__ out) {
    __shared__ float2 bufA[1024];
    __shared__ float2 bufB[1024];
    int row = blockIdx.x, tid = threadIdx.x;
    const float* pr = g_of_re + (size_t)row * 513;
    const float* pi = g_of_im + (size_t)row * 513;
    for (int i = tid; i < 1024; i += 256) {
        float re, im;
        if (i < 513) { re = pr[i];        im =  pi[i]; }
        else         { re = pr[1024 - i]; im = -pi[1024 - i]; }
        bufA[i] = make_float2(re, im);
    }
    __syncthreads();
    fft1024_shared(bufA, bufB, 1.0f, tid);
    int b = row >> 9, c = row & 511;
    float* po = out + (size_t)b * 524288 + c;
    for (int i = tid; i < 1024; i += 256)
        po[(size_t)i * 512] = bufA[i].x * 0.03125f;
}

// ---------------- launch ---------------------------------------------------
extern "C" void kernel_launch(void* const* d_in, const int* in_sizes, int n_in,
                              void* d_out, int out_size) {
    const float* q    = (const float*)d_in[0];
    const float* k    = (const float*)d_in[1];
    const float* v    = (const float*)d_in[2];
    const float* W    = (const float*)d_in[3];
    const float* bias = (const float*)d_in[4];
    float* out = (float*)d_out;

    const int attn_smem = 6 * 64 * AP * (int)sizeof(float);   // 99840 B
    cudaFuncSetAttribute(attn_kernel,
                         cudaFuncAttributeMaxDynamicSharedMemorySize, attn_smem);

    twiddle_kernel<<<1, 512>>>();
    conv_glu_kernel<<<dim3(256, 8), 256>>>(q, W, bias);
    rfft_kernel<<<NROW, 256>>>(nullptr, 0);
    rfft_kernel<<<NROW, 256>>>(k, 1);
    rfft_kernel<<<NROW, 256>>>(v, 2);
    attn_kernel<<<dim3(9, 128), 256, attn_smem>>>();
    irfft_kernel<<<NROW, 256>>>(out);
}

// round 3
// speedup vs baseline: 1.0110x; 1.0110x over previous
#include <cuda_runtime.h>
#include <math.h>

#define B_   16
#define L_   1024
#define H_   8
#define E_   64
#define D_   512
#define LF   513
#define NROW 8192            // B_*D_

// ---------------- device scratch (no cudaMalloc allowed) -------------------
__device__ float  g_q2t[B_ * D_ * L_];
__device__ float  g_qf_re[NROW * LF];
__device__ float  g_qf_im[NROW * LF];
__device__ float  g_kf_re[NROW * LF];
__device__ float  g_kf_im[NROW * LF];
__device__ float  g_vf_re[NROW * LF];
__device__ float  g_vf_im[NROW * LF];
__device__ float  g_of_re[NROW * LF];
__device__ float  g_of_im[NROW * LF];
__device__ float2 g_tw[512];

// ---------------- packed f32x2 helpers ------------------------------------
__device__ __forceinline__ unsigned long long pk2(float lo, float hi) {
    unsigned long long r;
    asm("mov.b64 %0, {%1, %2};" : "=l"(r) : "f"(lo), "f"(hi));
    return r;
}
__device__ __forceinline__ void upk2(unsigned long long v, float& lo, float& hi) {
    asm("mov.b64 {%0, %1}, %2;" : "=f"(lo), "=f"(hi) : "l"(v));
}
__device__ __forceinline__ unsigned long long ffma2(unsigned long long a,
                                                    unsigned long long b,
                                                    unsigned long long c) {
    unsigned long long d;
    asm("fma.rn.f32x2 %0, %1, %2, %3;" : "=l"(d) : "l"(a), "l"(b), "l"(c));
    return d;
}
// packed sign flip on the ALU pipe (not fma)
__device__ __forceinline__ unsigned long long neg2(unsigned long long a) {
    return a ^ 0x8000000080000000ULL;
}
__device__ __forceinline__ float sigmoidf_(float x) {
    return 1.0f / (1.0f + expf(-x));
}

// swizzled row base: rows >=32 shifted +2 floats so rows r and r+32 never
// share an 8B bank for stride-4-row LDS.64 access (row stride 66 floats)
__device__ __forceinline__ int rowbase(int r) {
    return r * 66 + ((r >> 5) << 1);
}

// ---------------- twiddle table: exp(+2*pi*i*j/1024) -----------------------
__global__ void twiddle_kernel() {
    int j = threadIdx.x;
    if (j < 512) {
        float s, c;
        sincosf(6.283185307179586f * (float)j * (1.0f / 1024.0f), &s, &c);
        g_tw[j] = make_float2(c, s);
    }
}

// ---------------- Conv1d(512->1024,k=3,p=1) + GLU -> g_q2t[b,c,l] ----------
__global__ __launch_bounds__(256) void conv_glu_kernel(
        const float* __restrict__ q, const float* __restrict__ W,
        const float* __restrict__ bias) {
    __shared__ __align__(16) float pool[7200];
    float* sx  = pool;               // [16 ic][66 l]
    float* swa = pool + 1056;        // [48 r][64 oc]  r = ic*3+kw
    float* swg = pool + 1056 + 3072;

    int b   = blockIdx.x >> 4;
    int l0  = (blockIdx.x & 15) << 6;
    int oc0 = blockIdx.y << 6;
    int tid = threadIdx.x;
    int tx  = tid & 15, ty = tid >> 4;

    unsigned long long pa[4][2], pg[4][2];
#pragma unroll
    for (int i = 0; i < 4; i++) {
        pa[i][0] = pa[i][1] = 0ull;
        pg[i][0] = pg[i][1] = 0ull;
    }

    for (int ic0 = 0; ic0 < 512; ic0 += 16) {
        __syncthreads();
#pragma unroll
        for (int t = 0; t < 5; t++) {
            int idx = tid + (t << 8);
            if (idx < 1056) {
                int li = idx >> 4, kk = idx & 15;
                int l = l0 - 1 + li;
                float v = 0.0f;
                if ((unsigned)l < 1024u)
                    v = q[((size_t)b * 1024 + l) * 512 + ic0 + kk];
                sx[kk * 66 + li] = v;
            }
        }
#pragma unroll
        for (int t = 0; t < 12; t++) {
            int idx = tid + (t << 8);
            int oc = idx / 48, r = idx % 48;
            swa[r * 64 + oc] = W[(size_t)(oc0 + oc) * 1536 + ic0 * 3 + r];
        }
#pragma unroll
        for (int t = 0; t < 12; t++) {
            int idx = tid + (t << 8);
            int oc = idx / 48, r = idx % 48;
            swg[r * 64 + oc] = W[(size_t)(512 + oc0 + oc) * 1536 + ic0 * 3 + r];
        }
        __syncthreads();

#pragma unroll
        for (int kk = 0; kk < 16; kk++) {
            unsigned long long xm[4], x0[4], xp[4];
#pragma unroll
            for (int yl = 0; yl < 4; yl++) {
                int li = (ty << 2) + yl;
                float a  = sx[kk * 66 + li];
                float b2 = sx[kk * 66 + li + 1];
                float c2 = sx[kk * 66 + li + 2];
                xm[yl] = pk2(a, a); x0[yl] = pk2(b2, b2); xp[yl] = pk2(c2, c2);
            }
#pragma unroll
            for (int xl2 = 0; xl2 < 2; xl2++) {
                int oc = (tx << 2) + (xl2 << 1);
                unsigned long long wa0 = *(const unsigned long long*)(swa + (kk * 3 + 0) * 64 + oc);
                unsigned long long wa1 = *(const unsigned long long*)(swa + (kk * 3 + 1) * 64 + oc);
                unsigned long long wa2 = *(const unsigned long long*)(swa + (kk * 3 + 2) * 64 + oc);
                unsigned long long wg0 = *(const unsigned long long*)(swg + (kk * 3 + 0) * 64 + oc);
                unsigned long long wg1 = *(const unsigned long long*)(swg + (kk * 3 + 1) * 64 + oc);
                unsigned long long wg2 = *(const unsigned long long*)(swg + (kk * 3 + 2) * 64 + oc);
#pragma unroll
                for (int yl = 0; yl < 4; yl++) {
                    pa[yl][xl2] = ffma2(xm[yl], wa0, pa[yl][xl2]);
                    pa[yl][xl2] = ffma2(x0[yl], wa1, pa[yl][xl2]);
                    pa[yl][xl2] = ffma2(xp[yl], wa2, pa[yl][xl2]);
                    pg[yl][xl2] = ffma2(xm[yl], wg0, pg[yl][xl2]);
                    pg[yl][xl2] = ffma2(x0[yl], wg1, pg[yl][xl2]);
                    pg[yl][xl2] = ffma2(xp[yl], wg2, pg[yl][xl2]);
                }
            }
        }
    }

    __syncthreads();
    float* st = pool;                // [64 oc][65 l]
#pragma unroll
    for (int yl = 0; yl < 4; yl++) {
#pragma unroll
        for (int xl2 = 0; xl2 < 2; xl2++) {
            float a0, a1, g0, g1;
            upk2(pa[yl][xl2], a0, a1);
            upk2(pg[yl][xl2], g0, g1);
            int oc = (tx << 2) + (xl2 << 1);
            a0 += bias[oc0 + oc];       a1 += bias[oc0 + oc + 1];
            g0 += bias[512 + oc0 + oc]; g1 += bias[512 + oc0 + oc + 1];
            int li = (ty << 2) + yl;
            st[oc * 65 + li]       = a0 * sigmoidf_(g0);
            st[(oc + 1) * 65 + li] = a1 * sigmoidf_(g1);
        }
    }
    __syncthreads();
#pragma unroll
    for (int t = 0; t < 16; t++) {
        int idx = tid + (t << 8);
        int c = idx >> 6, li = idx & 63;
        g_q2t[((size_t)b * 512 + oc0 + c) * 1024 + l0 + li] = st[c * 65 + li];
    }
}

// ---------------- 1024-pt radix-2 Stockham (DIF, natural order) ------------
__device__ __forceinline__ void fft1024_shared(float2* bufA, float2* bufB,
                                               float sgn, int tid) {
    float2* src = bufA;
    float2* dst = bufB;
    int m = 1;
#pragma unroll
    for (int stage = 0; stage < 10; stage++) {
#pragma unroll
        for (int u = 0; u < 2; u++) {
            int idx = tid + (u << 8);
            float2 c0 = src[idx];
            float2 c1 = src[idx + 512];
            int k = idx & (m - 1);
            int o = idx + (idx - k);
            float2 w = g_tw[idx - k];
            float wy = w.y * sgn;
            float trx = c0.x - c1.x, trY = c0.y - c1.y;
            dst[o]     = make_float2(c0.x + c1.x, c0.y + c1.y);
            dst[o + m] = make_float2(w.x * trx - wy * trY, w.x * trY + wy * trx);
        }
        __syncthreads();
        float2* t = src; src = dst; dst = t;
        m <<= 1;
    }
}

// which: 0 = q (g_q2t contiguous), 1 = k, 2 = v ([B,S,H,E] strided)
__global__ __launch_bounds__(256) void rfft_kernel(const float* __restrict__ in,
                                                   int which) {
    __shared__ float2 bufA[1024];
    __shared__ float2 bufB[1024];
    int row = blockIdx.x, tid = threadIdx.x;
    if (which == 0) {
        const float* p = g_q2t + (size_t)row * 1024;
        for (int i = tid; i < 1024; i += 256) bufA[i] = make_float2(p[i], 0.0f);
    } else {
        const float* p = in + (size_t)(row >> 9) * 524288 + (row & 511);
        for (int i = tid; i < 1024; i += 256)
            bufA[i] = make_float2(p[(size_t)i * 512], 0.0f);
    }
    __syncthreads();
    fft1024_shared(bufA, bufB, -1.0f, tid);
    float* ore = (which == 0) ? g_qf_re : (which == 1) ? g_kf_re : g_vf_re;
    float* oim = (which == 0) ? g_qf_im : (which == 1) ? g_kf_im : g_vf_im;
    for (int i = tid; i < 513; i += 256) {
        float2 vv = bufA[i];
        ore[(size_t)row * 513 + i] = vv.x * 0.03125f;
        oim[(size_t)row * 513 + i] = vv.y * 0.03125f;
    }
}

// ---------------- fused frequency attention, f32x2-packed ------------------
// Reduction axis packed in pairs: GEMM1 packs e, GEMM2 packs y. All operands
// load as LDS.64 from reduction-contiguous smem tiles; signs via XOR.
__global__ __launch_bounds__(256) void attn_kernel() {
    extern __shared__ float sm[];
    float* Qre = sm;                  // [x][e] packed-e
    float* Qim = sm + 4224;
    float* Ure = sm + 8448;           // K: [y][e]; later V: [e][y]
    float* Uim = sm + 12672;
    float* Tre = sm + 16896;          // [x][y] packed-y
    float* Tim = sm + 21120;

    int bh  = blockIdx.y;
    int x0  = blockIdx.x << 6;
    int tid = threadIdx.x;
    int tx  = tid & 15, ty = tid >> 4;
    size_t base = (size_t)bh * 64 * 513;

    // Q tile: gmem [e][x] -> smem [x][e] (transpose; gmem read coalesced in x)
#pragma unroll
    for (int t = 0; t < 16; t++) {
        int idx = tid + (t << 8);
        int e = idx >> 6, xi = idx & 63;
        int x = x0 + xi;
        float vr = 0.0f, vi = 0.0f;
        if (x < 513) {
            vr = g_qf_re[base + (size_t)e * 513 + x];
            vi = g_qf_im[base + (size_t)e * 513 + x];
        }
        int a = rowbase(xi) + e;
        Qre[a] = vr;
        Qim[a] = vi;
    }

    // row bases (float offsets) for this thread's micro-tile
    int qb[4], kb[4];
#pragma unroll
    for (int i = 0; i < 4; i++) qb[i] = rowbase((ty << 2) + i);
#pragma unroll
    for (int j = 0; j < 4; j++) kb[j] = rowbase((tx << 2) + j);

    unsigned long long ore_p[4][4], oim_p[4][4];
#pragma unroll
    for (int i = 0; i < 4; i++)
#pragma unroll
        for (int j = 0; j < 4; j++) { ore_p[i][j] = 0ull; oim_p[i][j] = 0ull; }
    float Dacc[4] = {};

    for (int yt = 0; yt < 9; yt++) {
        int y0 = yt << 6;
        __syncthreads();   // prior GEMM2's V reads complete
        // K tile: gmem [e][y] -> smem [y][e] (transpose)
#pragma unroll
        for (int t = 0; t < 16; t++) {
            int idx = tid + (t << 8);
            int e = idx >> 6, yi = idx & 63;
            int y = y0 + yi;
            float vr = 0.0f, vi = 0.0f;
            if (y < 513) {
                vr = g_kf_re[base + (size_t)e * 513 + y];
                vi = g_kf_im[base + (size_t)e * 513 + y];
            }
            int a = rowbase(yi) + e;
            Ure[a] = vr;
            Uim[a] = vi;
        }
        __syncthreads();

        // GEMM1: s[x,y] = sum_e qf*conj(kf), packed over e-pairs
        unsigned long long sre_p[4][4], sim_p[4][4];
#pragma unroll
        for (int i = 0; i < 4; i++)
#pragma unroll
            for (int j = 0; j < 4; j++) { sre_p[i][j] = 0ull; sim_p[i][j] = 0ull; }

        for (int e2 = 0; e2 < 32; e2++) {
            unsigned long long qr[4], qi[4], qrn[4], kr[4], ki[4];
            int off = e2 << 1;
#pragma unroll
            for (int i = 0; i < 4; i++) {
                qr[i] = *(const unsigned long long*)(Qre + qb[i] + off);
                qi[i] = *(const unsigned long long*)(Qim + qb[i] + off);
                qrn[i] = neg2(qr[i]);
            }
#pragma unroll
            for (int j = 0; j < 4; j++) {
                kr[j] = *(const unsigned long long*)(Ure + kb[j] + off);
                ki[j] = *(const unsigned long long*)(Uim + kb[j] + off);
            }
#pragma unroll
            for (int i = 0; i < 4; i++)
#pragma unroll
                for (int j = 0; j < 4; j++) {
                    sre_p[i][j] = ffma2(qr[i],  kr[j], sre_p[i][j]);
                    sre_p[i][j] = ffma2(qi[i],  ki[j], sre_p[i][j]);
                    sim_p[i][j] = ffma2(qi[i],  kr[j], sim_p[i][j]);
                    sim_p[i][j] = ffma2(qrn[i], ki[j], sim_p[i][j]);
                }
        }
        __syncthreads();   // all K reads done (U about to be overwritten)

        // gating epilogue -> T tile [x][y] + D partials
#pragma unroll
        for (int i = 0; i < 4; i++)
#pragma unroll
            for (int j = 0; j < 4; j++) {
                float a0, a1, b0, b1;
                upk2(sre_p[i][j], a0, a1);
                upk2(sim_p[i][j], b0, b1);
                float sr = (a0 + a1) * 0.125f;
                float si = (b0 + b1) * 0.125f;
                float mg = sqrtf(sr * sr + si * si);
                float w  = 1.0f + sigmoidf_(mg);
                Dacc[i] += mg * w;
                int a = qb[i] + (tx << 2) + j;
                Tre[a] = sr * w;
                Tim[a] = si * w;
            }
        // V tile: gmem [e][y] -> smem [e][y] (direct, y contiguous)
#pragma unroll
        for (int t = 0; t < 16; t++) {
            int idx = tid + (t << 8);
            int e = idx >> 6, yi = idx & 63;
            int y = y0 + yi;
            float vr = 0.0f, vi = 0.0f;
            if (y < 513) {
                vr = g_vf_re[base + (size_t)e * 513 + y];
                vi = g_vf_im[base + (size_t)e * 513 + y];
            }
            int a = rowbase(e) + yi;
            Ure[a] = vr;
            Uim[a] = vi;
        }
        __syncthreads();

        // GEMM2: of[x,e] += sum_y T[x,y]*V[e,y], packed over y-pairs
        for (int y2 = 0; y2 < 32; y2++) {
            unsigned long long tr[4], ti[4], tin[4], vr[4], vi[4];
            int off = y2 << 1;
#pragma unroll
            for (int i = 0; i < 4; i++) {
                tr[i] = *(const unsigned long long*)(Tre + qb[i] + off);
                ti[i] = *(const unsigned long long*)(Tim + qb[i] + off);
                tin[i] = neg2(ti[i]);
            }
#pragma unroll
            for (int j = 0; j < 4; j++) {
                vr[j] = *(const unsigned long long*)(Ure + kb[j] + off);
                vi[j] = *(const unsigned long long*)(Uim + kb[j] + off);
            }
#pragma unroll
            for (int i = 0; i < 4; i++)
#pragma unroll
                for (int j = 0; j < 4; j++) {
                    ore_p[i][j] = ffma2(tr[i],  vr[j], ore_p[i][j]);
                    ore_p[i][j] = ffma2(tin[i], vi[j], ore_p[i][j]);
                    oim_p[i][j] = ffma2(tr[i],  vi[j], oim_p[i][j]);
                    oim_p[i][j] = ffma2(ti[i],  vr[j], oim_p[i][j]);
                }
        }
    }

    // reduce D over tx lanes (bits 0..3 of lane id)
#pragma unroll
    for (int i = 0; i < 4; i++) {
        float dsum = Dacc[i];
        dsum += __shfl_xor_sync(0xffffffffu, dsum, 1);
        dsum += __shfl_xor_sync(0xffffffffu, dsum, 2);
        dsum += __shfl_xor_sync(0xffffffffu, dsum, 4);
        dsum += __shfl_xor_sync(0xffffffffu, dsum, 8);
        Dacc[i] = 1.0f / fmaxf(dsum, 1e-12f);
    }
#pragma unroll
    for (int i = 0; i < 4; i++) {
        int x = x0 + (ty << 2) + i;
        if (x < 513) {
#pragma unroll
            for (int j = 0; j < 4; j++) {
                int e = (tx << 2) + j;
                float a0, a1, b0, b1;
                upk2(ore_p[i][j], a0, a1);
                upk2(oim_p[i][j], b0, b1);
                g_of_re[base + (size_t)e * 513 + x] = (a0 + a1) * Dacc[i];
                g_of_im[base + (size_t)e * 513 + x] = (b0 + b1) * Dacc[i];
            }
        }
    }
}

// ---------------- irfft (ortho) + scatter to out[b,l,h,e] ------------------
__global__ __launch_bounds__(256) void irfft_kernel(float* __restrict__ out) {
    __shared__ float2 bufA[1024];
    __shared__ float2 bufB[1024];
    int row = blockIdx.x, tid = threadIdx.x;
    const float* pr = g_of_re + (size_t)row * 513;
    const float* pi = g_of_im + (size_t)row * 513;
    for (int i = tid; i < 1024; i += 256) {
        float re, im;
        if (i < 513) { re = pr[i];        im =  pi[i]; }
        else         { re = pr[1024 - i]; im = -pi[1024 - i]; }
        bufA[i] = make_float2(re, im);
    }
    __syncthreads();
    fft1024_shared(bufA, bufB, 1.0f, tid);
    int b = row >> 9, c = row & 511;
    float* po = out + (size_t)b * 524288 + c;
    for (int i = tid; i < 1024; i += 256)
        po[(size_t)i * 512] = bufA[i].x * 0.03125f;
}

// ---------------- launch ---------------------------------------------------
extern "C" void kernel_launch(void* const* d_in, const int* in_sizes, int n_in,
                              void* d_out, int out_size) {
    const float* q    = (const float*)d_in[0];
    const float* k    = (const float*)d_in[1];
    const float* v    = (const float*)d_in[2];
    const float* W    = (const float*)d_in[3];
    const float* bias = (const float*)d_in[4];
    float* out = (float*)d_out;

    const int attn_smem = 25344 * (int)sizeof(float);   // 101376 B
    cudaFuncSetAttribute(attn_kernel,
                         cudaFuncAttributeMaxDynamicSharedMemorySize, attn_smem);

    twiddle_kernel<<<1, 512>>>();
    conv_glu_kernel<<<dim3(256, 8), 256>>>(q, W, bias);
    rfft_kernel<<<NROW, 256>>>(nullptr, 0);
    rfft_kernel<<<NROW, 256>>>(k, 1);
    rfft_kernel<<<NROW, 256>>>(v, 2);
    attn_kernel<<<dim3(9, 128), 256, attn_smem>>>();
    irfft_kernel<<<NROW, 256>>>(out);
}